// round 16
// baseline (speedup 1.0000x reference)
#include <cuda_runtime.h>
#include <cuda_fp16.h>
#include <cstdint>
#include <math.h>

#define DIM      64
#define NREL     16
#define NCOLS    (NREL * DIM)        // 1024
#define MAX_N    120000
#define MAX_E    1600000

// ---- scratch ----
__device__ __align__(256) __half g_trans[(size_t)MAX_N * NCOLS];
__device__ __align__(256) __half g_embh[(size_t)MAX_N * DIM];     // fp16 emb
__device__ __align__(256) __half g_wh[NREL * DIM * DIM];          // fp16 W, pre-swizzled tiles
__device__ __align__(256) float  g_ex[MAX_E];
__device__ __align__(256) float  g_denom[MAX_N];

__device__ __forceinline__ uint32_t smem_u32(const void* p) {
    uint32_t a;
    asm("{ .reg .u64 t; cvta.to.shared.u64 t, %1; cvt.u32.u64 %0, t; }"
        : "=r"(a) : "l"(p));
    return a;
}

// ---- cp.async helpers ----
__device__ __forceinline__ void cp_async16(uint32_t smem, const void* g) {
    asm volatile("cp.async.cg.shared.global [%0], [%1], 16;" :: "r"(smem), "l"(g));
}
#define CP_COMMIT() asm volatile("cp.async.commit_group;" ::: "memory")
#define CP_WAIT0()  asm volatile("cp.async.wait_group 0;" ::: "memory")

// ---- warp-mma helpers ----
__device__ __forceinline__ void ldsm_x4(uint32_t addr, uint32_t* r) {
    asm volatile("ldmatrix.sync.aligned.m8n8.x4.shared.b16 {%0,%1,%2,%3}, [%4];"
        : "=r"(r[0]), "=r"(r[1]), "=r"(r[2]), "=r"(r[3]) : "r"(addr));
}
__device__ __forceinline__ void ldsm_x4_t(uint32_t addr, uint32_t* r) {
    asm volatile("ldmatrix.sync.aligned.m8n8.x4.trans.shared.b16 {%0,%1,%2,%3}, [%4];"
        : "=r"(r[0]), "=r"(r[1]), "=r"(r[2]), "=r"(r[3]) : "r"(addr));
}
__device__ __forceinline__ void stsm_x4(uint32_t addr, uint32_t r0, uint32_t r1,
                                        uint32_t r2, uint32_t r3) {
    asm volatile("stmatrix.sync.aligned.m8n8.x4.shared.b16 [%0], {%1,%2,%3,%4};"
        :: "r"(addr), "r"(r0), "r"(r1), "r"(r2), "r"(r3) : "memory");
}
__device__ __forceinline__ void mma_fp16(float* c, const uint32_t* a,
                                         uint32_t b0, uint32_t b1) {
    asm volatile(
        "mma.sync.aligned.m16n8k16.row.col.f32.f16.f16.f32 "
        "{%0,%1,%2,%3}, {%4,%5,%6,%7}, {%8,%9}, {%0,%1,%2,%3};"
        : "+f"(c[0]), "+f"(c[1]), "+f"(c[2]), "+f"(c[3])
        : "r"(a[0]), "r"(a[1]), "r"(a[2]), "r"(a[3]), "r"(b0), "r"(b1));
}

// smem: A (16 KB) + B double (2x8 KB) + OUT double (2x16 KB) = 64 KB
#define SM_A    0
#define SM_B    (SM_A + 128 * 128)
#define SM_OUT  (SM_B + 2 * 64 * 128)
#define SM_TOT  (SM_OUT + 2 * 128 * 128)   // 65536 B

#define SWZ(row, colb) (((uint32_t)(row)) * 128u + (((uint32_t)(colb)) ^ ((((uint32_t)(row)) & 7u) << 4)))

// ---- K0: convert emb->fp16, W->fp16 pre-swizzled tiles, zero denom ----
__global__ __launch_bounds__(256) void prep_kernel(
    const float* __restrict__ emb, const float* __restrict__ W, int M)
{
    int i = blockIdx.x * 256 + threadIdx.x;
    int nf4 = M * (DIM / 4);
    if (i < nf4) {
        float4 v = ((const float4*)emb)[i];
        __half2 a = __floats2half2_rn(v.x, v.y);
        __half2 b = __floats2half2_rn(v.z, v.w);
        ((uint2*)g_embh)[i] = make_uint2(*(uint32_t*)&a, *(uint32_t*)&b);
    }
    if (i < NREL * DIM * DIM) {
        int rel = i >> 12;
        int d   = (i >> 6) & 63;
        int n   = i & 63;
        *(__half*)((char*)g_wh + rel * 8192 + SWZ(d, n * 2)) =
            __float2half_rn(W[i]);
    }
    if (i < M) g_denom[i] = 0.0f;
}

// ---- K1: fp16 warp-MMA GEMM; 128-row tiles; cp.async; pipelined epilogue (R13) ----
__global__ __launch_bounds__(256, 3)
void gemm_kernel(int M)
{
    extern __shared__ char smem[];
    const uint32_t sb = smem_u32(smem);
    const int tid  = threadIdx.x;
    const int wid  = tid >> 5;
    const int lane = tid & 31;
    const int m0   = blockIdx.x * 128;

    // --- stage A via cp.async: 128 rows x 8 chunks of 16B = 1024 chunks ---
    #pragma unroll
    for (int p = 0; p < 4; p++) {
        int idx = tid + p * 256;          // 0..1023; row = idx>>3, c = idx&7
        int row = idx >> 3;
        int c   = idx & 7;
        int gm  = m0 + row;
        uint32_t dstp = sb + SM_A + SWZ(row, c * 16);
        if (gm < M) {
            cp_async16(dstp, g_embh + (size_t)gm * DIM + c * 8);
        } else {
            *(uint4*)(smem + (dstp - sb)) = make_uint4(0, 0, 0, 0);
        }
    }
    // --- stage B[0] via cp.async (pre-swizzled 8 KB tile = 512 chunks) ---
    #pragma unroll
    for (int p = 0; p < 2; p++) {
        int idx = tid + p * 256;
        cp_async16(sb + SM_B + idx * 16, (const char*)g_wh + idx * 16);
    }
    CP_COMMIT();
    CP_WAIT0();
    __syncthreads();

    // warp grid: 4 row strips x 2 col strips
    const int wrow = (wid & 3) * 32;
    const int wcol = (wid >> 2) * 32;

    const int a_midx = lane >> 3, a_r = lane & 7;
    const int a_colb0 = (a_midx >> 1) * 16;
    const int b_i = lane & 7, b_half = lane >> 3;
    const int b_krow0 = (b_half & 1) * 8 + b_i;
    const int b_ncol0 = (b_half >> 1) * 16;

    const uint32_t st_off = SWZ(wrow + (lane & 7), (wcol + (lane >> 3) * 8) * 2);

    for (int rrel = 0; rrel < NREL; rrel++) {
        const int cur = rrel & 1;
        const uint32_t bbuf = sb + SM_B + cur * 8192;

        // stage next relation's B via cp.async (overlaps MMA)
        if (rrel + 1 < NREL) {
            const char* wn = (const char*)g_wh + (size_t)(rrel + 1) * 8192;
            uint32_t nb = sb + SM_B + (1 - cur) * 8192;
            #pragma unroll
            for (int p = 0; p < 2; p++) {
                int idx = tid + p * 256;
                cp_async16(nb + idx * 16, wn + idx * 16);
            }
            CP_COMMIT();
        }

        float c[2][4][4];
        #pragma unroll
        for (int mt = 0; mt < 2; mt++)
            #pragma unroll
            for (int nt = 0; nt < 4; nt++)
                #pragma unroll
                for (int j = 0; j < 4; j++) c[mt][nt][j] = 0.0f;

        #pragma unroll
        for (int ks = 0; ks < 4; ks++) {
            uint32_t a0[4], a1[4];
            {
                int ar0 = wrow + (a_midx & 1) * 8 + a_r;
                ldsm_x4(sb + SM_A + SWZ(ar0,      ks * 32 + a_colb0), a0);
                ldsm_x4(sb + SM_A + SWZ(ar0 + 16, ks * 32 + a_colb0), a1);
            }
            #pragma unroll
            for (int n2 = 0; n2 < 2; n2++) {
                uint32_t b[4];
                int krow = ks * 16 + b_krow0;
                int colb = (wcol + n2 * 16) * 2 + b_ncol0;
                ldsm_x4_t(bbuf + SWZ(krow, colb), b);
                mma_fp16(c[0][n2 * 2 + 0], a0, b[0], b[1]);
                mma_fp16(c[0][n2 * 2 + 1], a0, b[2], b[3]);
                mma_fp16(c[1][n2 * 2 + 0], a1, b[0], b[1]);
                mma_fp16(c[1][n2 * 2 + 1], a1, b[2], b[3]);
            }
        }

        // copy out PREVIOUS relation's OUT buffer (overlaps this rel's MMA tail)
        if (rrel > 0) {
            const char* ob = smem + SM_OUT + (1 - cur) * 16384;
            #pragma unroll
            for (int p = 0; p < 4; p++) {
                int idx  = tid + p * 256;
                int row  = idx >> 3;
                int ch16 = idx & 7;
                int gm   = m0 + row;
                if (gm < M) {
                    uint4 v = *(const uint4*)(ob + SWZ(row, ch16 * 16));
                    *(uint4*)&g_trans[(size_t)gm * NCOLS + (rrel - 1) * DIM + ch16 * 8] = v;
                }
            }
        }

        // stsm this relation's fragments into OUT[cur]
        {
            const uint32_t st_addr = sb + SM_OUT + cur * 16384 + st_off;
            #pragma unroll
            for (int mt = 0; mt < 2; mt++)
                #pragma unroll
                for (int h = 0; h < 2; h++) {
                    uint32_t v[4];
                    #pragma unroll
                    for (int g = 0; g < 4; g++) {
                        __half2 hv = __floats2half2_rn(c[mt][g][h * 2], c[mt][g][h * 2 + 1]);
                        v[g] = *(uint32_t*)&hv;
                    }
                    stsm_x4(st_addr + (mt * 16 + h * 8) * 128, v[0], v[1], v[2], v[3]);
                }
        }
        CP_WAIT0();        // B[next] landed
        __syncthreads();   // OUT[cur] staged, OUT[1-cur] drained
    }

    // final copy: relation NREL-1 lives in OUT[1]
    {
        const char* ob = smem + SM_OUT + 16384;
        #pragma unroll
        for (int p = 0; p < 4; p++) {
            int idx  = tid + p * 256;
            int row  = idx >> 3;
            int ch16 = idx & 7;
            int gm   = m0 + row;
            if (gm < M) {
                uint4 v = *(const uint4*)(ob + SWZ(row, ch16 * 16));
                *(uint4*)&g_trans[(size_t)gm * NCOLS + (NREL - 1) * DIM + ch16 * 8] = v;
            }
        }
    }
}

// ---- K2: 8 lanes/edge, 4 edges per group, CLAMPED indices (MLP=8, no guards) ----
__global__ __launch_bounds__(256) void att_kernel(
    const int* __restrict__ src, const int* __restrict__ dst,
    const int* __restrict__ typ, const float* __restrict__ rel, int E)
{
    __shared__ __half s_relh[NREL * DIM];
    const int tid = threadIdx.x;
    #pragma unroll
    for (int i = tid; i < NREL * DIM / 2; i += 256) {
        float2 v = ((const float2*)rel)[i];
        ((__half2*)s_relh)[i] = __floats2half2_rn(v.x, v.y);
    }
    __syncthreads();

    const int lane = tid & 31;
    const int grp  = lane >> 3;
    const int sub  = lane & 7;
    const int warp = (blockIdx.x * 256 + tid) >> 5;
    const int eb   = warp * 16 + grp * 4;

    // clamped indices: all loads always valid (E >= 1); guard only at store
    int ec[4], s[4], d[4], r[4];
    #pragma unroll
    for (int j = 0; j < 4; j++) {
        ec[j] = min(eb + j, E - 1);
        s[j] = src[ec[j]];
        d[j] = dst[ec[j]];
        r[j] = typ[ec[j]];
    }

    // 8 unconditional back-to-back 16B gathers (MLP=8 per lane)
    uint4 t[4], h[4];
    #pragma unroll
    for (int j = 0; j < 4; j++) {
        t[j] = *(const uint4*)(g_trans + (size_t)s[j] * NCOLS + r[j] * DIM + sub * 8);
        h[j] = *(const uint4*)(g_trans + (size_t)d[j] * NCOLS + r[j] * DIM + sub * 8);
    }

    float p[4];
    #pragma unroll
    for (int j = 0; j < 4; j++) {
        p[j] = 0.0f;
        uint4 rv = *(const uint4*)(s_relh + r[j] * DIM + sub * 8);
        const uint32_t* tw = (const uint32_t*)&t[j];
        const uint32_t* hw = (const uint32_t*)&h[j];
        const uint32_t* rw = (const uint32_t*)&rv;
        #pragma unroll
        for (int q = 0; q < 4; q++) {
            __half2 arg = __hadd2(*(const __half2*)&hw[q], *(const __half2*)&rw[q]);
            uint32_t th;
            asm("tanh.approx.f16x2 %0, %1;" : "=r"(th) : "r"(*(uint32_t*)&arg));
            float2 tf = __half22float2(*(const __half2*)&tw[q]);
            float2 tt = __half22float2(*(const __half2*)&th);
            p[j] += tf.x * tt.x + tf.y * tt.y;
        }
    }
    #pragma unroll
    for (int o = 1; o < 8; o <<= 1)
        #pragma unroll
        for (int j = 0; j < 4; j++)
            p[j] += __shfl_xor_sync(0xffffffffu, p[j], o);

    if (sub == 0) {
        #pragma unroll
        for (int j = 0; j < 4; j++) {
            if (eb + j < E) {
                float ex = __expf(p[j]);
                g_ex[eb + j] = ex;
                atomicAdd(&g_denom[d[j]], ex);
            }
        }
    }
}

// ---- K3: normalize, 4 edges per thread ----
__global__ void norm_kernel(const int* __restrict__ dst, float* __restrict__ out, int E) {
    int i4 = (blockIdx.x * blockDim.x + threadIdx.x) * 4;
    if (i4 + 3 < E) {
        float4 ex = *(const float4*)&g_ex[i4];
        int4   dd = *(const int4*)&dst[i4];
        float4 o;
        o.x = ex.x / g_denom[dd.x];
        o.y = ex.y / g_denom[dd.y];
        o.z = ex.z / g_denom[dd.z];
        o.w = ex.w / g_denom[dd.w];
        *(float4*)&out[i4] = o;
    } else {
        for (int i = i4; i < E; i++) out[i] = g_ex[i] / g_denom[dst[i]];
    }
}

extern "C" void kernel_launch(void* const* d_in, const int* in_sizes, int n_in,
                              void* d_out, int out_size)
{
    const float* emb = (const float*)d_in[0];
    const float* rel = (const float*)d_in[1];
    const float* W   = (const float*)d_in[2];
    const int*   src = (const int*)d_in[3];
    const int*   dst = (const int*)d_in[4];
    const int*   typ = (const int*)d_in[5];
    float*       out = (float*)d_out;

    int M = in_sizes[0] / DIM;
    int E = in_sizes[3];

    static bool attr_set = false;
    if (!attr_set) {
        cudaFuncSetAttribute(gemm_kernel,
                             cudaFuncAttributeMaxDynamicSharedMemorySize, SM_TOT);
        attr_set = true;
    }

    int prep_threads = M * (DIM / 4);
    prep_kernel<<<(prep_threads + 255) / 256, 256>>>(emb, W, M);
    gemm_kernel<<<(M + 127) / 128, 256, SM_TOT>>>(M);
    att_kernel<<<(E + 127) / 128, 256>>>(src, dst, typ, rel, E);
    norm_kernel<<<(E / 4 + 255) / 256, 256>>>(dst, out, E);
}

// round 17
// speedup vs baseline: 1.1005x; 1.1005x over previous
#include <cuda_runtime.h>
#include <cuda_fp16.h>
#include <cstdint>
#include <math.h>

#define DIM      64
#define NREL     16
#define NCOLS    (NREL * DIM)        // 1024
#define MAX_N    120000
#define MAX_E    1600000

// ---- scratch ----
__device__ __align__(256) __half g_trans[(size_t)MAX_N * NCOLS];
__device__ __align__(256) __half g_embh[(size_t)MAX_N * DIM];     // fp16 emb
__device__ __align__(256) __half g_wh[NREL * DIM * DIM];          // fp16 W, pre-swizzled tiles
__device__ __align__(256) float  g_ex[MAX_E];
__device__ __align__(256) float  g_denom[MAX_N];

__device__ __forceinline__ uint32_t smem_u32(const void* p) {
    uint32_t a;
    asm("{ .reg .u64 t; cvta.to.shared.u64 t, %1; cvt.u32.u64 %0, t; }"
        : "=r"(a) : "l"(p));
    return a;
}

// ---- cp.async helpers ----
__device__ __forceinline__ void cp_async16(uint32_t smem, const void* g) {
    asm volatile("cp.async.cg.shared.global [%0], [%1], 16;" :: "r"(smem), "l"(g));
}
#define CP_COMMIT() asm volatile("cp.async.commit_group;" ::: "memory")
#define CP_WAIT0()  asm volatile("cp.async.wait_group 0;" ::: "memory")

// ---- warp-mma helpers ----
__device__ __forceinline__ void ldsm_x4(uint32_t addr, uint32_t* r) {
    asm volatile("ldmatrix.sync.aligned.m8n8.x4.shared.b16 {%0,%1,%2,%3}, [%4];"
        : "=r"(r[0]), "=r"(r[1]), "=r"(r[2]), "=r"(r[3]) : "r"(addr));
}
__device__ __forceinline__ void ldsm_x4_t(uint32_t addr, uint32_t* r) {
    asm volatile("ldmatrix.sync.aligned.m8n8.x4.trans.shared.b16 {%0,%1,%2,%3}, [%4];"
        : "=r"(r[0]), "=r"(r[1]), "=r"(r[2]), "=r"(r[3]) : "r"(addr));
}
__device__ __forceinline__ void stsm_x4(uint32_t addr, uint32_t r0, uint32_t r1,
                                        uint32_t r2, uint32_t r3) {
    asm volatile("stmatrix.sync.aligned.m8n8.x4.shared.b16 [%0], {%1,%2,%3,%4};"
        :: "r"(addr), "r"(r0), "r"(r1), "r"(r2), "r"(r3) : "memory");
}
__device__ __forceinline__ void mma_fp16(float* c, const uint32_t* a,
                                         uint32_t b0, uint32_t b1) {
    asm volatile(
        "mma.sync.aligned.m16n8k16.row.col.f32.f16.f16.f32 "
        "{%0,%1,%2,%3}, {%4,%5,%6,%7}, {%8,%9}, {%0,%1,%2,%3};"
        : "+f"(c[0]), "+f"(c[1]), "+f"(c[2]), "+f"(c[3])
        : "r"(a[0]), "r"(a[1]), "r"(a[2]), "r"(a[3]), "r"(b0), "r"(b1));
}

// smem: A (16 KB) + B double (2x8 KB) + OUT double (2x16 KB) = 64 KB
#define SM_A    0
#define SM_B    (SM_A + 128 * 128)
#define SM_OUT  (SM_B + 2 * 64 * 128)
#define SM_TOT  (SM_OUT + 2 * 128 * 128)   // 65536 B

#define SWZ(row, colb) (((uint32_t)(row)) * 128u + (((uint32_t)(colb)) ^ ((((uint32_t)(row)) & 7u) << 4)))

// ---- K0: convert emb->fp16, W->fp16 pre-swizzled tiles, zero denom ----
__global__ __launch_bounds__(256) void prep_kernel(
    const float* __restrict__ emb, const float* __restrict__ W, int M)
{
    int i = blockIdx.x * 256 + threadIdx.x;
    int nf4 = M * (DIM / 4);
    if (i < nf4) {
        float4 v = ((const float4*)emb)[i];
        __half2 a = __floats2half2_rn(v.x, v.y);
        __half2 b = __floats2half2_rn(v.z, v.w);
        ((uint2*)g_embh)[i] = make_uint2(*(uint32_t*)&a, *(uint32_t*)&b);
    }
    if (i < NREL * DIM * DIM) {
        int rel = i >> 12;
        int d   = (i >> 6) & 63;
        int n   = i & 63;
        *(__half*)((char*)g_wh + rel * 8192 + SWZ(d, n * 2)) =
            __float2half_rn(W[i]);
    }
    if (i < M) g_denom[i] = 0.0f;
}

// ---- K1: fp16 warp-MMA GEMM; 128-row tiles; cp.async; pipelined epilogue (R13) ----
__global__ __launch_bounds__(256, 3)
void gemm_kernel(int M)
{
    extern __shared__ char smem[];
    const uint32_t sb = smem_u32(smem);
    const int tid  = threadIdx.x;
    const int wid  = tid >> 5;
    const int lane = tid & 31;
    const int m0   = blockIdx.x * 128;

    // --- stage A via cp.async: 128 rows x 8 chunks of 16B = 1024 chunks ---
    #pragma unroll
    for (int p = 0; p < 4; p++) {
        int idx = tid + p * 256;          // 0..1023; row = idx>>3, c = idx&7
        int row = idx >> 3;
        int c   = idx & 7;
        int gm  = m0 + row;
        uint32_t dstp = sb + SM_A + SWZ(row, c * 16);
        if (gm < M) {
            cp_async16(dstp, g_embh + (size_t)gm * DIM + c * 8);
        } else {
            *(uint4*)(smem + (dstp - sb)) = make_uint4(0, 0, 0, 0);
        }
    }
    // --- stage B[0] via cp.async (pre-swizzled 8 KB tile = 512 chunks) ---
    #pragma unroll
    for (int p = 0; p < 2; p++) {
        int idx = tid + p * 256;
        cp_async16(sb + SM_B + idx * 16, (const char*)g_wh + idx * 16);
    }
    CP_COMMIT();
    CP_WAIT0();
    __syncthreads();

    // warp grid: 4 row strips x 2 col strips
    const int wrow = (wid & 3) * 32;
    const int wcol = (wid >> 2) * 32;

    const int a_midx = lane >> 3, a_r = lane & 7;
    const int a_colb0 = (a_midx >> 1) * 16;
    const int b_i = lane & 7, b_half = lane >> 3;
    const int b_krow0 = (b_half & 1) * 8 + b_i;
    const int b_ncol0 = (b_half >> 1) * 16;

    const uint32_t st_off = SWZ(wrow + (lane & 7), (wcol + (lane >> 3) * 8) * 2);

    for (int rrel = 0; rrel < NREL; rrel++) {
        const int cur = rrel & 1;
        const uint32_t bbuf = sb + SM_B + cur * 8192;

        // stage next relation's B via cp.async (overlaps MMA)
        if (rrel + 1 < NREL) {
            const char* wn = (const char*)g_wh + (size_t)(rrel + 1) * 8192;
            uint32_t nb = sb + SM_B + (1 - cur) * 8192;
            #pragma unroll
            for (int p = 0; p < 2; p++) {
                int idx = tid + p * 256;
                cp_async16(nb + idx * 16, wn + idx * 16);
            }
            CP_COMMIT();
        }

        float c[2][4][4];
        #pragma unroll
        for (int mt = 0; mt < 2; mt++)
            #pragma unroll
            for (int nt = 0; nt < 4; nt++)
                #pragma unroll
                for (int j = 0; j < 4; j++) c[mt][nt][j] = 0.0f;

        #pragma unroll
        for (int ks = 0; ks < 4; ks++) {
            uint32_t a0[4], a1[4];
            {
                int ar0 = wrow + (a_midx & 1) * 8 + a_r;
                ldsm_x4(sb + SM_A + SWZ(ar0,      ks * 32 + a_colb0), a0);
                ldsm_x4(sb + SM_A + SWZ(ar0 + 16, ks * 32 + a_colb0), a1);
            }
            #pragma unroll
            for (int n2 = 0; n2 < 2; n2++) {
                uint32_t b[4];
                int krow = ks * 16 + b_krow0;
                int colb = (wcol + n2 * 16) * 2 + b_ncol0;
                ldsm_x4_t(bbuf + SWZ(krow, colb), b);
                mma_fp16(c[0][n2 * 2 + 0], a0, b[0], b[1]);
                mma_fp16(c[0][n2 * 2 + 1], a0, b[2], b[3]);
                mma_fp16(c[1][n2 * 2 + 0], a1, b[0], b[1]);
                mma_fp16(c[1][n2 * 2 + 1], a1, b[2], b[3]);
            }
        }

        // copy out PREVIOUS relation's OUT buffer (overlaps this rel's MMA tail)
        if (rrel > 0) {
            const char* ob = smem + SM_OUT + (1 - cur) * 16384;
            #pragma unroll
            for (int p = 0; p < 4; p++) {
                int idx  = tid + p * 256;
                int row  = idx >> 3;
                int ch16 = idx & 7;
                int gm   = m0 + row;
                if (gm < M) {
                    uint4 v = *(const uint4*)(ob + SWZ(row, ch16 * 16));
                    *(uint4*)&g_trans[(size_t)gm * NCOLS + (rrel - 1) * DIM + ch16 * 8] = v;
                }
            }
        }

        // stsm this relation's fragments into OUT[cur]
        {
            const uint32_t st_addr = sb + SM_OUT + cur * 16384 + st_off;
            #pragma unroll
            for (int mt = 0; mt < 2; mt++)
                #pragma unroll
                for (int h = 0; h < 2; h++) {
                    uint32_t v[4];
                    #pragma unroll
                    for (int g = 0; g < 4; g++) {
                        __half2 hv = __floats2half2_rn(c[mt][g][h * 2], c[mt][g][h * 2 + 1]);
                        v[g] = *(uint32_t*)&hv;
                    }
                    stsm_x4(st_addr + (mt * 16 + h * 8) * 128, v[0], v[1], v[2], v[3]);
                }
        }
        CP_WAIT0();        // B[next] landed
        __syncthreads();   // OUT[cur] staged, OUT[1-cur] drained
    }

    // final copy: relation NREL-1 lives in OUT[1]
    {
        const char* ob = smem + SM_OUT + 16384;
        #pragma unroll
        for (int p = 0; p < 4; p++) {
            int idx  = tid + p * 256;
            int row  = idx >> 3;
            int ch16 = idx & 7;
            int gm   = m0 + row;
            if (gm < M) {
                uint4 v = *(const uint4*)(ob + SWZ(row, ch16 * 16));
                *(uint4*)&g_trans[(size_t)gm * NCOLS + (NREL - 1) * DIM + ch16 * 8] = v;
            }
        }
    }
}

// ---- K2: 8 lanes/edge, 2 edges per group (measured best); clamped loads ----
__global__ __launch_bounds__(256) void att_kernel(
    const int* __restrict__ src, const int* __restrict__ dst,
    const int* __restrict__ typ, const float* __restrict__ rel, int E)
{
    __shared__ __half s_relh[NREL * DIM];
    const int tid = threadIdx.x;
    #pragma unroll
    for (int i = tid; i < NREL * DIM / 2; i += 256) {
        float2 v = ((const float2*)rel)[i];
        ((__half2*)s_relh)[i] = __floats2half2_rn(v.x, v.y);
    }
    __syncthreads();

    const int lane = tid & 31;
    const int grp  = lane >> 3;
    const int sub  = lane & 7;
    const int warp = (blockIdx.x * 256 + tid) >> 5;
    const int e0   = warp * 8 + grp * 2;
    const int e1   = e0 + 1;

    // clamped indices: loads always valid (E >= 1); validity only at store
    const int ec0 = min(e0, E - 1);
    const int ec1 = min(e1, E - 1);
    int s0 = src[ec0], d0 = dst[ec0], r0 = typ[ec0];
    int s1 = src[ec1], d1 = dst[ec1], r1 = typ[ec1];

    // 4 unconditional back-to-back 16B gathers (MLP=4 per lane — measured sweet spot)
    uint4 t0 = *(const uint4*)(g_trans + (size_t)s0 * NCOLS + r0 * DIM + sub * 8);
    uint4 h0 = *(const uint4*)(g_trans + (size_t)d0 * NCOLS + r0 * DIM + sub * 8);
    uint4 t1 = *(const uint4*)(g_trans + (size_t)s1 * NCOLS + r1 * DIM + sub * 8);
    uint4 h1 = *(const uint4*)(g_trans + (size_t)d1 * NCOLS + r1 * DIM + sub * 8);
    uint4 rv0 = *(const uint4*)(s_relh + r0 * DIM + sub * 8);
    uint4 rv1 = *(const uint4*)(s_relh + r1 * DIM + sub * 8);

    float p0 = 0.0f, p1 = 0.0f;
    {
        const uint32_t* tw = (const uint32_t*)&t0;
        const uint32_t* hw = (const uint32_t*)&h0;
        const uint32_t* rw = (const uint32_t*)&rv0;
        #pragma unroll
        for (int j = 0; j < 4; j++) {
            __half2 arg = __hadd2(*(const __half2*)&hw[j], *(const __half2*)&rw[j]);
            uint32_t th;
            asm("tanh.approx.f16x2 %0, %1;" : "=r"(th) : "r"(*(uint32_t*)&arg));
            float2 tf = __half22float2(*(const __half2*)&tw[j]);
            float2 tt = __half22float2(*(const __half2*)&th);
            p0 += tf.x * tt.x + tf.y * tt.y;
        }
    }
    {
        const uint32_t* tw = (const uint32_t*)&t1;
        const uint32_t* hw = (const uint32_t*)&h1;
        const uint32_t* rw = (const uint32_t*)&rv1;
        #pragma unroll
        for (int j = 0; j < 4; j++) {
            __half2 arg = __hadd2(*(const __half2*)&hw[j], *(const __half2*)&rw[j]);
            uint32_t th;
            asm("tanh.approx.f16x2 %0, %1;" : "=r"(th) : "r"(*(uint32_t*)&arg));
            float2 tf = __half22float2(*(const __half2*)&tw[j]);
            float2 tt = __half22float2(*(const __half2*)&th);
            p1 += tf.x * tt.x + tf.y * tt.y;
        }
    }
    #pragma unroll
    for (int o = 1; o < 8; o <<= 1) {
        p0 += __shfl_xor_sync(0xffffffffu, p0, o);
        p1 += __shfl_xor_sync(0xffffffffu, p1, o);
    }

    if (sub == 0) {
        if (e0 < E) {
            float ex = __expf(p0);
            g_ex[e0] = ex;
            atomicAdd(&g_denom[d0], ex);
        }
        if (e1 < E) {
            float ex = __expf(p1);
            g_ex[e1] = ex;
            atomicAdd(&g_denom[d1], ex);
        }
    }
}

// ---- K3: normalize, 4 edges per thread ----
__global__ void norm_kernel(const int* __restrict__ dst, float* __restrict__ out, int E) {
    int i4 = (blockIdx.x * blockDim.x + threadIdx.x) * 4;
    if (i4 + 3 < E) {
        float4 ex = *(const float4*)&g_ex[i4];
        int4   dd = *(const int4*)&dst[i4];
        float4 o;
        o.x = ex.x / g_denom[dd.x];
        o.y = ex.y / g_denom[dd.y];
        o.z = ex.z / g_denom[dd.z];
        o.w = ex.w / g_denom[dd.w];
        *(float4*)&out[i4] = o;
    } else {
        for (int i = i4; i < E; i++) out[i] = g_ex[i] / g_denom[dst[i]];
    }
}

extern "C" void kernel_launch(void* const* d_in, const int* in_sizes, int n_in,
                              void* d_out, int out_size)
{
    const float* emb = (const float*)d_in[0];
    const float* rel = (const float*)d_in[1];
    const float* W   = (const float*)d_in[2];
    const int*   src = (const int*)d_in[3];
    const int*   dst = (const int*)d_in[4];
    const int*   typ = (const int*)d_in[5];
    float*       out = (float*)d_out;

    int M = in_sizes[0] / DIM;
    int E = in_sizes[3];

    static bool attr_set = false;
    if (!attr_set) {
        cudaFuncSetAttribute(gemm_kernel,
                             cudaFuncAttributeMaxDynamicSharedMemorySize, SM_TOT);
        attr_set = true;
    }

    int prep_threads = M * (DIM / 4);
    prep_kernel<<<(prep_threads + 255) / 256, 256>>>(emb, W, M);
    gemm_kernel<<<(M + 127) / 128, 256, SM_TOT>>>(M);
    att_kernel<<<(E + 63) / 64, 256>>>(src, dst, typ, rel, E);
    norm_kernel<<<(E / 4 + 255) / 256, 256>>>(dst, out, E);
}